// round 6
// baseline (speedup 1.0000x reference)
#include <cuda_runtime.h>
#include <cuda_bf16.h>
#include <cstdint>

// Problem constants
#define TLEN 2048
#define BSZ  2
#define EMB  1024
#define NH   16
#define HD   64
#define BH   (BSZ*NH)     // 32
#define MROWS (TLEN*BSZ)  // 4096
#define THREE_E (3*EMB)   // 3072
#define KEFF  (3*EMB)     // tripled K for bf16x3 emulation (=3072)
#define KROWB (KEFF*2)    // bytes per row of converted operands (6144)
#define SCALING 0.125f

// ---------------------------------------------------------------------------
// Device-global scratch (allocations forbidden)
// ---------------------------------------------------------------------------
__device__ __nv_bfloat16 g_qh[BH*TLEN*HD];
__device__ __nv_bfloat16 g_ql[BH*TLEN*HD];
__device__ __nv_bfloat16 g_kh[BH*TLEN*HD];
__device__ __nv_bfloat16 g_kl[BH*TLEN*HD];
__device__ __nv_bfloat16 g_vh[BH*TLEN*HD];
__device__ __nv_bfloat16 g_vl[BH*TLEN*HD];
__device__ __nv_bfloat16 g_xa   [MROWS  * KEFF];    // X,    A-pattern (hi,hi,lo)
__device__ __nv_bfloat16 g_win  [THREE_E* KEFF];    // Win,  B-pattern (hi,lo,hi)
__device__ __nv_bfloat16 g_wout [EMB    * KEFF];    // Wout, B-pattern
__device__ __nv_bfloat16 g_attna[MROWS  * KEFF];    // attn, A-pattern

// ---------------------------------------------------------------------------
// PTX helpers — base sm_100 target only
// ---------------------------------------------------------------------------
__device__ __forceinline__ uint32_t smem_u32(const void* p) {
    uint32_t a;
    asm("{ .reg .u64 t; cvta.to.shared.u64 t, %1; cvt.u32.u64 %0, t; }" : "=r"(a) : "l"(p));
    return a;
}
#define CP_ASYNC16(dst, src) \
    asm volatile("cp.async.cg.shared.global [%0], [%1], 16;" :: "r"(dst), "l"(src))
#define CP_COMMIT() asm volatile("cp.async.commit_group;" ::: "memory")
#define CP_WAIT0()  asm volatile("cp.async.wait_group 0;" ::: "memory")
#define CP_WAIT1()  asm volatile("cp.async.wait_group 1;" ::: "memory")

#define LDSM_X4(r0, r1, r2, r3, addr) \
    asm volatile("ldmatrix.sync.aligned.m8n8.x4.shared.b16 {%0,%1,%2,%3}, [%4];" \
        : "=r"(r0), "=r"(r1), "=r"(r2), "=r"(r3) : "r"(addr))
#define LDSM_X4_T(r0, r1, r2, r3, addr) \
    asm volatile("ldmatrix.sync.aligned.m8n8.x4.trans.shared.b16 {%0,%1,%2,%3}, [%4];" \
        : "=r"(r0), "=r"(r1), "=r"(r2), "=r"(r3) : "r"(addr))

#define MMA16816(d, a, b) \
    asm volatile("mma.sync.aligned.m16n8k16.row.col.f32.bf16.bf16.f32 " \
        "{%0,%1,%2,%3}, {%4,%5,%6,%7}, {%8,%9}, {%0,%1,%2,%3};" \
        : "+f"((d)[0]), "+f"((d)[1]), "+f"((d)[2]), "+f"((d)[3]) \
        : "r"((a)[0]), "r"((a)[1]), "r"((a)[2]), "r"((a)[3]), \
          "r"((b)[0]), "r"((b)[1]))

__device__ __forceinline__ uint32_t packbf(__nv_bfloat16 x, __nv_bfloat16 y) {
    uint32_t o;
    asm("mov.b32 %0, {%1, %2};" : "=r"(o)
        : "h"(*(unsigned short*)&x), "h"(*(unsigned short*)&y));
    return o;
}
__device__ __forceinline__ void split2(float x, float y, uint32_t& hp, uint32_t& lp) {
    __nv_bfloat16 hx = __float2bfloat16(x), hy = __float2bfloat16(y);
    __nv_bfloat16 lx = __float2bfloat16(x - __bfloat162float(hx));
    __nv_bfloat16 ly = __float2bfloat16(y - __bfloat162float(hy));
    hp = packbf(hx, hy);
    lp = packbf(lx, ly);
}

// ---------------------------------------------------------------------------
// Conversion: fp32 [rows x 1024] -> bf16x3 [rows x 3072].
// patB=0 (A-pattern): segs hi,hi,lo.  patB=1 (B-pattern): segs hi,lo,hi.
// ---------------------------------------------------------------------------
__global__ __launch_bounds__(256) void cvt_kernel(const float* __restrict__ src,
                                                  __nv_bfloat16* __restrict__ dst,
                                                  int patB) {
    const int row = blockIdx.x;
    const int kc = threadIdx.x * 4;
    float4 v = *(const float4*)(src + row * EMB + kc);
    uint32_t h0, l0, h1, l1;
    split2(v.x, v.y, h0, l0);
    split2(v.z, v.w, h1, l1);
    uint2 hv = make_uint2(h0, h1);
    uint2 lv = make_uint2(l0, l1);
    __nv_bfloat16* base = dst + (size_t)row * KEFF + kc;
    *(uint2*)(base)            = hv;
    *(uint2*)(base + EMB)      = patB ? lv : hv;
    *(uint2*)(base + 2 * EMB)  = patB ? hv : lv;
}

// ---------------------------------------------------------------------------
// mma.sync bf16 GEMM: C[m][n] = sum_k A[m][k]*B[n][k], K=3072.
// Block 128x128, 8 warps (2x4), warp 64x32. K-chunk 64, 3-stage cp.async ring,
// ONE __syncthreads per chunk, double-buffered ldmatrix fragments.
// MODE 0: qkv epilogue -> bf16 hi/lo q/k/v buffers. MODE 1: fp32 out + bias.
// ---------------------------------------------------------------------------
#define TILE_M 128
#define TILE_N 128
#define KCH 64
#define NCHUNK (KEFF / KCH)   // 48
#define G_STRIDE 72
#define G_SB (G_STRIDE*2)     // 144 B row stride
#define G_MATB (128*G_SB)     // 18432 B per matrix
#define G_STAGEB (2*G_MATB)   // 36864 B per stage (A+B)
#define G_SMEM (3*G_STAGEB)   // 110592

template <int MODE>
__global__ __launch_bounds__(256, 1) void gemm_kernel(const __nv_bfloat16* __restrict__ A,
                                                      const __nv_bfloat16* __restrict__ B,
                                                      const float* __restrict__ bias,
                                                      float* __restrict__ out) {
    extern __shared__ char gsm[];
    const uint32_t sbase = smem_u32(gsm);

    const int tid = threadIdx.x;
    const int wid = tid >> 5, lane = tid & 31;
    const int m0 = blockIdx.y * TILE_M;
    const int n0 = blockIdx.x * TILE_N;
    const int warp_m = (wid >> 2) * 64;
    const int warp_n = (wid & 3) * 32;

    const char* Ab = (const char*)A + (size_t)m0 * KROWB;
    const char* Bb = (const char*)B + (size_t)n0 * KROWB;

    const int a_row = lane & 15;
    const int a_kof = (lane >> 4) << 3;
    const int b_row = (lane & 7) + ((lane & 16) >> 1);
    const int b_kof = ((lane >> 3) & 1) << 3;

    float acc[4][4][4];
    #pragma unroll
    for (int i = 0; i < 4; i++)
        #pragma unroll
        for (int j = 0; j < 4; j++)
            #pragma unroll
            for (int r = 0; r < 4; r++) acc[i][j][r] = 0.0f;

    auto load_chunk = [&](int c, int s) {
        const uint32_t da = sbase + s * G_STAGEB;
        const uint32_t db = da + G_MATB;
        const size_t ko = (size_t)c * (KCH * 2);
        #pragma unroll
        for (int i = 0; i < 4; i++) {
            int u = tid + i * 256;
            int r = u >> 3, seg = (u & 7) * 16;
            CP_ASYNC16(da + r * G_SB + seg, Ab + (size_t)r * KROWB + ko + seg);
        }
        #pragma unroll
        for (int i = 0; i < 4; i++) {
            int u = tid + i * 256;
            int r = u >> 3, seg = (u & 7) * 16;
            CP_ASYNC16(db + r * G_SB + seg, Bb + (size_t)r * KROWB + ko + seg);
        }
        CP_COMMIT();
    };

    auto ld_frags = [&](uint32_t da, uint32_t db, int k0,
                        uint32_t af[4][4], uint32_t bf[4][2]) {
        #pragma unroll
        for (int i = 0; i < 4; i++) {
            uint32_t addr = da + (warp_m + i * 16 + a_row) * G_SB + (k0 + a_kof) * 2;
            LDSM_X4(af[i][0], af[i][1], af[i][2], af[i][3], addr);
        }
        #pragma unroll
        for (int j2 = 0; j2 < 2; j2++) {
            uint32_t addr = db + (warp_n + j2 * 16 + b_row) * G_SB + (k0 + b_kof) * 2;
            LDSM_X4(bf[j2*2][0], bf[j2*2][1], bf[j2*2+1][0], bf[j2*2+1][1], addr);
        }
    };

    load_chunk(0, 0);
    load_chunk(1, 1);
    for (int c = 0; c < NCHUNK; c++) {
        const int s = c % 3;
        if (c == NCHUNK - 1) CP_WAIT0(); else CP_WAIT1();
        __syncthreads();
        if (c + 2 < NCHUNK) load_chunk(c + 2, (c + 2) % 3);

        const uint32_t da = sbase + s * G_STAGEB;
        const uint32_t db = da + G_MATB;
        uint32_t af[2][4][4], bf[2][4][2];
        ld_frags(da, db, 0, af[0], bf[0]);
        #pragma unroll
        for (int k = 0; k < 4; k++) {
            const int cur = k & 1;
            if (k < 3) ld_frags(da, db, (k + 1) * 16, af[cur ^ 1], bf[cur ^ 1]);
            #pragma unroll
            for (int i = 0; i < 4; i++)
                #pragma unroll
                for (int j = 0; j < 4; j++)
                    MMA16816(acc[i][j], af[cur][i], bf[cur][j]);
        }
    }

    // Epilogue
    const int sec = n0 >> 10;
    const float sc = (MODE == 0 && sec == 0) ? SCALING : 1.0f;
    __nv_bfloat16* hb = (sec == 0) ? g_qh : (sec == 1) ? g_kh : g_vh;
    __nv_bfloat16* lb = (sec == 0) ? g_ql : (sec == 1) ? g_kl : g_vl;

    #pragma unroll
    for (int i = 0; i < 4; i++) {
        #pragma unroll
        for (int j = 0; j < 4; j++) {
            const int f = n0 + warp_n + j * 8 + (lane & 3) * 2;
            const float b0 = bias[f], b1 = bias[f + 1];
            #pragma unroll
            for (int half = 0; half < 2; half++) {
                const int m = m0 + warp_m + i * 16 + (lane >> 2) + half * 8;
                float ox = (acc[i][j][half * 2 + 0] + b0) * sc;
                float oy = (acc[i][j][half * 2 + 1] + b1) * sc;
                if (MODE == 0) {
                    const int t = m >> 1, bq = m & 1;
                    const int rel = f & 1023, h = rel >> 6, d = rel & 63;
                    size_t idx = (((size_t)(bq * 16 + h) * TLEN + t) * HD + d);
                    uint32_t hp, lp;
                    split2(ox, oy, hp, lp);
                    *(uint32_t*)(hb + idx) = hp;
                    *(uint32_t*)(lb + idx) = lp;
                } else {
                    *(float2*)(out + (size_t)m * EMB + f) = make_float2(ox, oy);
                }
            }
        }
    }
}

// ---------------------------------------------------------------------------
// Tensor-core flash attention. Block = (head, 128-q-tile). 8 warps x 16 rows.
// KV chunk 128 keys, 3-stage cp.async ring, single sync per chunk.
// 3-term bf16 hi/lo for QK^T and PV. Writes outproj A-pattern to g_attna.
// ---------------------------------------------------------------------------
#define AT_STRIDE 72
#define AT_SB (AT_STRIDE*2)      // 144 B
#define AT_MATB (128*AT_SB)      // 18432 B per matrix
#define AT_STAGEB (4*AT_MATB)    // 73728 B (Khi,Klo,Vhi,Vlo)
#define AT_SMEM (3*AT_STAGEB)    // 221184
#define NKV (TLEN/128)           // 16

__global__ __launch_bounds__(256, 1) void attn_tc_kernel() {
    extern __shared__ char asmb[];
    const uint32_t sb = smem_u32(asmb);
    const int tid = threadIdx.x;
    const int wid = tid >> 5, lane = tid & 31;
    const int head = blockIdx.y;
    const int qb = blockIdx.x * 128;
    const int wr0 = wid * 16;
    const int r = lane >> 2, cb = (lane & 3) * 2;

    const int b_row = (lane & 7) + ((lane & 16) >> 1);
    const int b_kof = ((lane >> 3) & 1) << 3;
    const int v_row = lane & 15;
    const int v_cof = (lane >> 4) << 3;

    // Q fragments direct from gmem (rows wr0..wr0+15, d 0..63, hi+lo)
    const __nv_bfloat16* qhp = g_qh + ((size_t)head * TLEN + qb + wr0) * HD;
    const __nv_bfloat16* qlp = g_ql + ((size_t)head * TLEN + qb + wr0) * HD;
    uint32_t qfh[4][4], qfl[4][4];
    #pragma unroll
    for (int ks = 0; ks < 4; ks++) {
        qfh[ks][0] = *(const uint32_t*)(qhp + (size_t)(r    ) * HD + ks * 16 + cb);
        qfh[ks][1] = *(const uint32_t*)(qhp + (size_t)(r + 8) * HD + ks * 16 + cb);
        qfh[ks][2] = *(const uint32_t*)(qhp + (size_t)(r    ) * HD + ks * 16 + 8 + cb);
        qfh[ks][3] = *(const uint32_t*)(qhp + (size_t)(r + 8) * HD + ks * 16 + 8 + cb);
        qfl[ks][0] = *(const uint32_t*)(qlp + (size_t)(r    ) * HD + ks * 16 + cb);
        qfl[ks][1] = *(const uint32_t*)(qlp + (size_t)(r + 8) * HD + ks * 16 + cb);
        qfl[ks][2] = *(const uint32_t*)(qlp + (size_t)(r    ) * HD + ks * 16 + 8 + cb);
        qfl[ks][3] = *(const uint32_t*)(qlp + (size_t)(r + 8) * HD + ks * 16 + 8 + cb);
    }

    const char* Khg = (const char*)(g_kh + (size_t)head * TLEN * HD);
    const char* Klg = (const char*)(g_kl + (size_t)head * TLEN * HD);
    const char* Vhg = (const char*)(g_vh + (size_t)head * TLEN * HD);
    const char* Vlg = (const char*)(g_vl + (size_t)head * TLEN * HD);

    auto load_chunk = [&](int c, int s) {
        const uint32_t st = sb + s * AT_STAGEB;
        const size_t go = (size_t)c * 128 * (HD * 2);
        #pragma unroll
        for (int i = 0; i < 4; i++) {
            int u = tid + i * 256;
            int rr = u >> 3, seg = (u & 7) * 16;
            uint32_t doff = rr * AT_SB + seg;
            size_t soff = go + (size_t)rr * (HD * 2) + seg;
            CP_ASYNC16(st + 0 * AT_MATB + doff, Khg + soff);
            CP_ASYNC16(st + 1 * AT_MATB + doff, Klg + soff);
            CP_ASYNC16(st + 2 * AT_MATB + doff, Vhg + soff);
            CP_ASYNC16(st + 3 * AT_MATB + doff, Vlg + soff);
        }
        CP_COMMIT();
    };

    float m0 = -3.0e38f, m1 = -3.0e38f, l0 = 0.0f, l1 = 0.0f;
    float O[8][4];
    #pragma unroll
    for (int nt = 0; nt < 8; nt++)
        #pragma unroll
        for (int j = 0; j < 4; j++) O[nt][j] = 0.0f;

    load_chunk(0, 0);
    load_chunk(1, 1);
    for (int c = 0; c < NKV; c++) {
        const int s = c % 3;
        if (c == NKV - 1) CP_WAIT0(); else CP_WAIT1();
        __syncthreads();
        if (c + 2 < NKV) load_chunk(c + 2, (c + 2) % 3);

        const uint32_t st = sb + s * AT_STAGEB;

        // ---- S = Q K^T (3-term), 8 keygroups of 16 keys ----
        float sacc[8][8];
        #pragma unroll
        for (int kg = 0; kg < 8; kg++)
            #pragma unroll
            for (int j = 0; j < 8; j++) sacc[kg][j] = 0.0f;

        #pragma unroll
        for (int kg = 0; kg < 8; kg++) {
            #pragma unroll
            for (int ks = 0; ks < 4; ks++) {
                uint32_t bh[4], bl[4];
                uint32_t ah = st + 0 * AT_MATB + (kg * 16 + b_row) * AT_SB + (ks * 16 + b_kof) * 2;
                uint32_t al = st + 1 * AT_MATB + (kg * 16 + b_row) * AT_SB + (ks * 16 + b_kof) * 2;
                LDSM_X4(bh[0], bh[1], bh[2], bh[3], ah);
                LDSM_X4(bl[0], bl[1], bl[2], bl[3], al);
                MMA16816(&sacc[kg][0], qfh[ks], bh);
                MMA16816(&sacc[kg][4], qfh[ks], bh + 2);
                MMA16816(&sacc[kg][0], qfh[ks], bl);
                MMA16816(&sacc[kg][4], qfh[ks], bl + 2);
                MMA16816(&sacc[kg][0], qfl[ks], bh);
                MMA16816(&sacc[kg][4], qfl[ks], bh + 2);
            }
        }

        // ---- online softmax (rows r and r+8) ----
        float mx0 = -3.0e38f, mx1 = -3.0e38f;
        #pragma unroll
        for (int kg = 0; kg < 8; kg++) {
            mx0 = fmaxf(mx0, fmaxf(fmaxf(sacc[kg][0], sacc[kg][1]),
                                   fmaxf(sacc[kg][4], sacc[kg][5])));
            mx1 = fmaxf(mx1, fmaxf(fmaxf(sacc[kg][2], sacc[kg][3]),
                                   fmaxf(sacc[kg][6], sacc[kg][7])));
        }
        mx0 = fmaxf(mx0, __shfl_xor_sync(0xffffffff, mx0, 1));
        mx0 = fmaxf(mx0, __shfl_xor_sync(0xffffffff, mx0, 2));
        mx1 = fmaxf(mx1, __shfl_xor_sync(0xffffffff, mx1, 1));
        mx1 = fmaxf(mx1, __shfl_xor_sync(0xffffffff, mx1, 2));

        float mn0 = fmaxf(m0, mx0), mn1 = fmaxf(m1, mx1);
        float al0 = __expf(m0 - mn0), al1 = __expf(m1 - mn1);
        m0 = mn0; m1 = mn1;

        float rs0 = 0.0f, rs1 = 0.0f;
        uint32_t pfh[8][4], pfl[8][4];
        #pragma unroll
        for (int kg = 0; kg < 8; kg++) {
            float p0 = __expf(sacc[kg][0] - mn0), p1 = __expf(sacc[kg][1] - mn0);
            float p2 = __expf(sacc[kg][2] - mn1), p3 = __expf(sacc[kg][3] - mn1);
            float p4 = __expf(sacc[kg][4] - mn0), p5 = __expf(sacc[kg][5] - mn0);
            float p6 = __expf(sacc[kg][6] - mn1), p7 = __expf(sacc[kg][7] - mn1);
            rs0 += p0 + p1 + p4 + p5;
            rs1 += p2 + p3 + p6 + p7;
            split2(p0, p1, pfh[kg][0], pfl[kg][0]);
            split2(p2, p3, pfh[kg][1], pfl[kg][1]);
            split2(p4, p5, pfh[kg][2], pfl[kg][2]);
            split2(p6, p7, pfh[kg][3], pfl[kg][3]);
        }
        rs0 += __shfl_xor_sync(0xffffffff, rs0, 1);
        rs0 += __shfl_xor_sync(0xffffffff, rs0, 2);
        rs1 += __shfl_xor_sync(0xffffffff, rs1, 1);
        rs1 += __shfl_xor_sync(0xffffffff, rs1, 2);
        l0 = l0 * al0 + rs0;
        l1 = l1 * al1 + rs1;

        #pragma unroll
        for (int nt = 0; nt < 8; nt++) {
            O[nt][0] *= al0; O[nt][1] *= al0;
            O[nt][2] *= al1; O[nt][3] *= al1;
        }

        // ---- O += P V (3-term) ----
        #pragma unroll
        for (int kg = 0; kg < 8; kg++) {
            #pragma unroll
            for (int dt = 0; dt < 4; dt++) {
                uint32_t vh[4], vl[4];
                uint32_t ahh = st + 2 * AT_MATB + (kg * 16 + v_row) * AT_SB + (dt * 16 + v_cof) * 2;
                uint32_t all = st + 3 * AT_MATB + (kg * 16 + v_row) * AT_SB + (dt * 16 + v_cof) * 2;
                LDSM_X4_T(vh[0], vh[1], vh[2], vh[3], ahh);
                LDSM_X4_T(vl[0], vl[1], vl[2], vl[3], all);
                MMA16816(O[2*dt],     pfh[kg], vh);
                MMA16816(O[2*dt + 1], pfh[kg], vh + 2);
                MMA16816(O[2*dt],     pfh[kg], vl);
                MMA16816(O[2*dt + 1], pfh[kg], vl + 2);
                MMA16816(O[2*dt],     pfl[kg], vh);
                MMA16816(O[2*dt + 1], pfl[kg], vh + 2);
            }
        }
    }

    // ---- epilogue: normalize, write outproj A-pattern (hi,hi,lo) ----
    const float inv0 = 1.0f / l0, inv1 = 1.0f / l1;
    const int bb = head >> 4, hh = head & 15;
    const int mr0 = (qb + wr0 + r) * 2 + bb;
    const int mr8 = (qb + wr0 + r + 8) * 2 + bb;
    #pragma unroll
    for (int nt = 0; nt < 8; nt++) {
        const int e = hh * 64 + nt * 8 + cb;
        uint32_t hp, lp;
        split2(O[nt][0] * inv0, O[nt][1] * inv0, hp, lp);
        __nv_bfloat16* base = g_attna + (size_t)mr0 * KEFF + e;
        *(uint32_t*)(base)           = hp;
        *(uint32_t*)(base + EMB)     = hp;
        *(uint32_t*)(base + 2*EMB)   = lp;
        split2(O[nt][2] * inv1, O[nt][3] * inv1, hp, lp);
        base = g_attna + (size_t)mr8 * KEFF + e;
        *(uint32_t*)(base)           = hp;
        *(uint32_t*)(base + EMB)     = hp;
        *(uint32_t*)(base + 2*EMB)   = lp;
    }
}

// ---------------------------------------------------------------------------
extern "C" void kernel_launch(void* const* d_in, const int* in_sizes, int n_in,
                              void* d_out, int out_size) {
    (void)in_sizes; (void)n_in; (void)out_size;
    const float* x     = (const float*)d_in[0];
    const float* w_in  = (const float*)d_in[1];
    const float* b_in  = (const float*)d_in[2];
    const float* w_out = (const float*)d_in[3];
    const float* b_out = (const float*)d_in[4];
    float* out = (float*)d_out;

    cudaFuncSetAttribute(gemm_kernel<0>, cudaFuncAttributeMaxDynamicSharedMemorySize, G_SMEM);
    cudaFuncSetAttribute(gemm_kernel<1>, cudaFuncAttributeMaxDynamicSharedMemorySize, G_SMEM);
    cudaFuncSetAttribute(attn_tc_kernel, cudaFuncAttributeMaxDynamicSharedMemorySize, AT_SMEM);

    __nv_bfloat16 *gxa, *gwin, *gwout, *gattna;
    cudaGetSymbolAddress((void**)&gxa, g_xa);
    cudaGetSymbolAddress((void**)&gwin, g_win);
    cudaGetSymbolAddress((void**)&gwout, g_wout);
    cudaGetSymbolAddress((void**)&gattna, g_attna);

    // 1) convert operands to bf16x3
    cvt_kernel<<<MROWS, 256>>>(x, gxa, 0);
    cvt_kernel<<<THREE_E, 256>>>(w_in, gwin, 1);
    cvt_kernel<<<EMB, 256>>>(w_out, gwout, 1);
    // 2) QKV projection -> bf16 hi/lo q/k/v
    gemm_kernel<0><<<dim3(THREE_E / TILE_N, MROWS / TILE_M), 256, G_SMEM>>>(gxa, gwin, b_in, nullptr);
    // 3) tensor-core flash attention -> g_attna (A-pattern)
    attn_tc_kernel<<<dim3(TLEN / 128, BH), 256, AT_SMEM>>>();
    // 4) output projection
    gemm_kernel<1><<<dim3(EMB / TILE_N, MROWS / TILE_M), 256, G_SMEM>>>(gattna, gwout, b_out, out);
}

// round 7
// speedup vs baseline: 1.0041x; 1.0041x over previous
#include <cuda_runtime.h>
#include <cuda_bf16.h>
#include <cstdint>

// Problem constants
#define TLEN 2048
#define BSZ  2
#define EMB  1024
#define NH   16
#define HD   64
#define BH   (BSZ*NH)     // 32
#define MROWS (TLEN*BSZ)  // 4096
#define THREE_E (3*EMB)   // 3072
#define KEFF  (3*EMB)     // tripled K for bf16x3 emulation (=3072)
#define KROWB (KEFF*2)    // bytes per row of converted operands (6144)
#define SCALING 0.125f

// ---------------------------------------------------------------------------
// Device-global scratch (allocations forbidden)
// ---------------------------------------------------------------------------
__device__ __nv_bfloat16 g_qh[BH*TLEN*HD];
__device__ __nv_bfloat16 g_ql[BH*TLEN*HD];
__device__ __nv_bfloat16 g_kh[BH*TLEN*HD];
__device__ __nv_bfloat16 g_kl[BH*TLEN*HD];
__device__ __nv_bfloat16 g_vh[BH*TLEN*HD];
__device__ __nv_bfloat16 g_vl[BH*TLEN*HD];
__device__ __nv_bfloat16 g_xa   [MROWS  * KEFF];    // X,    A-pattern (hi,hi,lo)
__device__ __nv_bfloat16 g_win  [THREE_E* KEFF];    // Win,  B-pattern (hi,lo,hi)
__device__ __nv_bfloat16 g_wout [EMB    * KEFF];    // Wout, B-pattern
__device__ __nv_bfloat16 g_attna[MROWS  * KEFF];    // attn, A-pattern

// ---------------------------------------------------------------------------
// PTX helpers — base sm_100 target only
// ---------------------------------------------------------------------------
__device__ __forceinline__ uint32_t smem_u32(const void* p) {
    uint32_t a;
    asm("{ .reg .u64 t; cvta.to.shared.u64 t, %1; cvt.u32.u64 %0, t; }" : "=r"(a) : "l"(p));
    return a;
}
#define CP_ASYNC16(dst, src) \
    asm volatile("cp.async.cg.shared.global [%0], [%1], 16;" :: "r"(dst), "l"(src))
#define CP_COMMIT() asm volatile("cp.async.commit_group;" ::: "memory")
#define CP_WAIT0()  asm volatile("cp.async.wait_group 0;" ::: "memory")
#define CP_WAIT1()  asm volatile("cp.async.wait_group 1;" ::: "memory")

#define LDSM_X4(r0, r1, r2, r3, addr) \
    asm volatile("ldmatrix.sync.aligned.m8n8.x4.shared.b16 {%0,%1,%2,%3}, [%4];" \
        : "=r"(r0), "=r"(r1), "=r"(r2), "=r"(r3) : "r"(addr))
#define LDSM_X4_T(r0, r1, r2, r3, addr) \
    asm volatile("ldmatrix.sync.aligned.m8n8.x4.trans.shared.b16 {%0,%1,%2,%3}, [%4];" \
        : "=r"(r0), "=r"(r1), "=r"(r2), "=r"(r3) : "r"(addr))

#define MMA16816(d, a, b) \
    asm volatile("mma.sync.aligned.m16n8k16.row.col.f32.bf16.bf16.f32 " \
        "{%0,%1,%2,%3}, {%4,%5,%6,%7}, {%8,%9}, {%0,%1,%2,%3};" \
        : "+f"((d)[0]), "+f"((d)[1]), "+f"((d)[2]), "+f"((d)[3]) \
        : "r"((a)[0]), "r"((a)[1]), "r"((a)[2]), "r"((a)[3]), \
          "r"((b)[0]), "r"((b)[1]))

__device__ __forceinline__ uint32_t packbf(__nv_bfloat16 x, __nv_bfloat16 y) {
    uint32_t o;
    asm("mov.b32 %0, {%1, %2};" : "=r"(o)
        : "h"(*(unsigned short*)&x), "h"(*(unsigned short*)&y));
    return o;
}
__device__ __forceinline__ void split2(float x, float y, uint32_t& hp, uint32_t& lp) {
    __nv_bfloat16 hx = __float2bfloat16(x), hy = __float2bfloat16(y);
    __nv_bfloat16 lx = __float2bfloat16(x - __bfloat162float(hx));
    __nv_bfloat16 ly = __float2bfloat16(y - __bfloat162float(hy));
    hp = packbf(hx, hy);
    lp = packbf(lx, ly);
}

// ---------------------------------------------------------------------------
// Conversion: fp32 [rows x 1024] -> bf16x3 [rows x 3072].
// patB=0 (A-pattern): segs hi,hi,lo.  patB=1 (B-pattern): segs hi,lo,hi.
// ---------------------------------------------------------------------------
__global__ __launch_bounds__(256) void cvt_kernel(const float* __restrict__ src,
                                                  __nv_bfloat16* __restrict__ dst,
                                                  int patB) {
    const int row = blockIdx.x;
    const int kc = threadIdx.x * 4;
    float4 v = *(const float4*)(src + row * EMB + kc);
    uint32_t h0, l0, h1, l1;
    split2(v.x, v.y, h0, l0);
    split2(v.z, v.w, h1, l1);
    uint2 hv = make_uint2(h0, h1);
    uint2 lv = make_uint2(l0, l1);
    __nv_bfloat16* base = dst + (size_t)row * KEFF + kc;
    *(uint2*)(base)            = hv;
    *(uint2*)(base + EMB)      = patB ? lv : hv;
    *(uint2*)(base + 2 * EMB)  = patB ? hv : lv;
}

// ---------------------------------------------------------------------------
// mma.sync bf16 GEMM: C[m][n] = sum_k A[m][k]*B[n][k], K=3072.
// Block 128x128, 8 warps (2x4), warp 64x32. K-chunk 64, 3-stage cp.async ring,
// ONE __syncthreads per chunk, double-buffered ldmatrix fragments.
// MODE 0: qkv epilogue -> bf16 hi/lo q/k/v buffers. MODE 1: fp32 out + bias.
// ---------------------------------------------------------------------------
#define TILE_M 128
#define TILE_N 128
#define KCH 64
#define NCHUNK (KEFF / KCH)   // 48
#define G_STRIDE 72
#define G_SB (G_STRIDE*2)     // 144 B row stride
#define G_MATB (128*G_SB)     // 18432 B per matrix
#define G_STAGEB (2*G_MATB)   // 36864 B per stage (A+B)
#define G_SMEM (3*G_STAGEB)   // 110592

template <int MODE>
__global__ __launch_bounds__(256, 1) void gemm_kernel(const __nv_bfloat16* __restrict__ A,
                                                      const __nv_bfloat16* __restrict__ B,
                                                      const float* __restrict__ bias,
                                                      float* __restrict__ out) {
    extern __shared__ char gsm[];
    const uint32_t sbase = smem_u32(gsm);

    const int tid = threadIdx.x;
    const int wid = tid >> 5, lane = tid & 31;
    const int m0 = blockIdx.y * TILE_M;
    const int n0 = blockIdx.x * TILE_N;
    const int warp_m = (wid >> 2) * 64;
    const int warp_n = (wid & 3) * 32;

    const char* Ab = (const char*)A + (size_t)m0 * KROWB;
    const char* Bb = (const char*)B + (size_t)n0 * KROWB;

    const int a_row = lane & 15;
    const int a_kof = (lane >> 4) << 3;
    const int b_row = (lane & 7) + ((lane & 16) >> 1);
    const int b_kof = ((lane >> 3) & 1) << 3;

    float acc[4][4][4];
    #pragma unroll
    for (int i = 0; i < 4; i++)
        #pragma unroll
        for (int j = 0; j < 4; j++)
            #pragma unroll
            for (int r = 0; r < 4; r++) acc[i][j][r] = 0.0f;

    auto load_chunk = [&](int c, int s) {
        const uint32_t da = sbase + s * G_STAGEB;
        const uint32_t db = da + G_MATB;
        const size_t ko = (size_t)c * (KCH * 2);
        #pragma unroll
        for (int i = 0; i < 4; i++) {
            int u = tid + i * 256;
            int r = u >> 3, seg = (u & 7) * 16;
            CP_ASYNC16(da + r * G_SB + seg, Ab + (size_t)r * KROWB + ko + seg);
        }
        #pragma unroll
        for (int i = 0; i < 4; i++) {
            int u = tid + i * 256;
            int r = u >> 3, seg = (u & 7) * 16;
            CP_ASYNC16(db + r * G_SB + seg, Bb + (size_t)r * KROWB + ko + seg);
        }
        CP_COMMIT();
    };

    auto ld_frags = [&](uint32_t da, uint32_t db, int k0,
                        uint32_t af[4][4], uint32_t bf[4][2]) {
        #pragma unroll
        for (int i = 0; i < 4; i++) {
            uint32_t addr = da + (warp_m + i * 16 + a_row) * G_SB + (k0 + a_kof) * 2;
            LDSM_X4(af[i][0], af[i][1], af[i][2], af[i][3], addr);
        }
        #pragma unroll
        for (int j2 = 0; j2 < 2; j2++) {
            uint32_t addr = db + (warp_n + j2 * 16 + b_row) * G_SB + (k0 + b_kof) * 2;
            LDSM_X4(bf[j2*2][0], bf[j2*2][1], bf[j2*2+1][0], bf[j2*2+1][1], addr);
        }
    };

    load_chunk(0, 0);
    load_chunk(1, 1);
    for (int c = 0; c < NCHUNK; c++) {
        const int s = c % 3;
        if (c == NCHUNK - 1) CP_WAIT0(); else CP_WAIT1();
        __syncthreads();
        if (c + 2 < NCHUNK) load_chunk(c + 2, (c + 2) % 3);

        const uint32_t da = sbase + s * G_STAGEB;
        const uint32_t db = da + G_MATB;
        uint32_t af[2][4][4], bf[2][4][2];
        ld_frags(da, db, 0, af[0], bf[0]);
        #pragma unroll
        for (int k = 0; k < 4; k++) {
            const int cur = k & 1;
            if (k < 3) ld_frags(da, db, (k + 1) * 16, af[cur ^ 1], bf[cur ^ 1]);
            #pragma unroll
            for (int i = 0; i < 4; i++)
                #pragma unroll
                for (int j = 0; j < 4; j++)
                    MMA16816(acc[i][j], af[cur][i], bf[cur][j]);
        }
    }

    // Epilogue
    const int sec = n0 >> 10;
    const float sc = (MODE == 0 && sec == 0) ? SCALING : 1.0f;
    __nv_bfloat16* hb = (sec == 0) ? g_qh : (sec == 1) ? g_kh : g_vh;
    __nv_bfloat16* lb = (sec == 0) ? g_ql : (sec == 1) ? g_kl : g_vl;

    #pragma unroll
    for (int i = 0; i < 4; i++) {
        #pragma unroll
        for (int j = 0; j < 4; j++) {
            const int f = n0 + warp_n + j * 8 + (lane & 3) * 2;
            const float b0 = bias[f], b1 = bias[f + 1];
            #pragma unroll
            for (int half = 0; half < 2; half++) {
                const int m = m0 + warp_m + i * 16 + (lane >> 2) + half * 8;
                float ox = (acc[i][j][half * 2 + 0] + b0) * sc;
                float oy = (acc[i][j][half * 2 + 1] + b1) * sc;
                if (MODE == 0) {
                    const int t = m >> 1, bq = m & 1;
                    const int rel = f & 1023, h = rel >> 6, d = rel & 63;
                    size_t idx = (((size_t)(bq * 16 + h) * TLEN + t) * HD + d);
                    uint32_t hp, lp;
                    split2(ox, oy, hp, lp);
                    *(uint32_t*)(hb + idx) = hp;
                    *(uint32_t*)(lb + idx) = lp;
                } else {
                    *(float2*)(out + (size_t)m * EMB + f) = make_float2(ox, oy);
                }
            }
        }
    }
}

// ---------------------------------------------------------------------------
// Tensor-core flash attention. Block = (head, 128-q-tile). 8 warps x 16 rows.
// KV chunk 128 keys, 3-stage cp.async ring, single sync per chunk.
// 3-term bf16 hi/lo for QK^T and PV. Writes outproj A-pattern to g_attna.
// ---------------------------------------------------------------------------
#define AT_STRIDE 72
#define AT_SB (AT_STRIDE*2)      // 144 B
#define AT_MATB (128*AT_SB)      // 18432 B per matrix
#define AT_STAGEB (4*AT_MATB)    // 73728 B (Khi,Klo,Vhi,Vlo)
#define AT_SMEM (3*AT_STAGEB)    // 221184
#define NKV (TLEN/128)           // 16

__global__ __launch_bounds__(256, 1) void attn_tc_kernel() {
    extern __shared__ char asmb[];
    const uint32_t sb = smem_u32(asmb);
    const int tid = threadIdx.x;
    const int wid = tid >> 5, lane = tid & 31;
    const int head = blockIdx.y;
    const int qb = blockIdx.x * 128;
    const int wr0 = wid * 16;
    const int r = lane >> 2, cb = (lane & 3) * 2;

    const int b_row = (lane & 7) + ((lane & 16) >> 1);
    const int b_kof = ((lane >> 3) & 1) << 3;
    const int v_row = lane & 15;
    const int v_cof = (lane >> 4) << 3;

    // Q fragments direct from gmem (rows wr0..wr0+15, d 0..63, hi+lo)
    const __nv_bfloat16* qhp = g_qh + ((size_t)head * TLEN + qb + wr0) * HD;
    const __nv_bfloat16* qlp = g_ql + ((size_t)head * TLEN + qb + wr0) * HD;
    uint32_t qfh[4][4], qfl[4][4];
    #pragma unroll
    for (int ks = 0; ks < 4; ks++) {
        qfh[ks][0] = *(const uint32_t*)(qhp + (size_t)(r    ) * HD + ks * 16 + cb);
        qfh[ks][1] = *(const uint32_t*)(qhp + (size_t)(r + 8) * HD + ks * 16 + cb);
        qfh[ks][2] = *(const uint32_t*)(qhp + (size_t)(r    ) * HD + ks * 16 + 8 + cb);
        qfh[ks][3] = *(const uint32_t*)(qhp + (size_t)(r + 8) * HD + ks * 16 + 8 + cb);
        qfl[ks][0] = *(const uint32_t*)(qlp + (size_t)(r    ) * HD + ks * 16 + cb);
        qfl[ks][1] = *(const uint32_t*)(qlp + (size_t)(r + 8) * HD + ks * 16 + cb);
        qfl[ks][2] = *(const uint32_t*)(qlp + (size_t)(r    ) * HD + ks * 16 + 8 + cb);
        qfl[ks][3] = *(const uint32_t*)(qlp + (size_t)(r + 8) * HD + ks * 16 + 8 + cb);
    }

    const char* Khg = (const char*)(g_kh + (size_t)head * TLEN * HD);
    const char* Klg = (const char*)(g_kl + (size_t)head * TLEN * HD);
    const char* Vhg = (const char*)(g_vh + (size_t)head * TLEN * HD);
    const char* Vlg = (const char*)(g_vl + (size_t)head * TLEN * HD);

    auto load_chunk = [&](int c, int s) {
        const uint32_t st = sb + s * AT_STAGEB;
        const size_t go = (size_t)c * 128 * (HD * 2);
        #pragma unroll
        for (int i = 0; i < 4; i++) {
            int u = tid + i * 256;
            int rr = u >> 3, seg = (u & 7) * 16;
            uint32_t doff = rr * AT_SB + seg;
            size_t soff = go + (size_t)rr * (HD * 2) + seg;
            CP_ASYNC16(st + 0 * AT_MATB + doff, Khg + soff);
            CP_ASYNC16(st + 1 * AT_MATB + doff, Klg + soff);
            CP_ASYNC16(st + 2 * AT_MATB + doff, Vhg + soff);
            CP_ASYNC16(st + 3 * AT_MATB + doff, Vlg + soff);
        }
        CP_COMMIT();
    };

    float m0 = -3.0e38f, m1 = -3.0e38f, l0 = 0.0f, l1 = 0.0f;
    float O[8][4];
    #pragma unroll
    for (int nt = 0; nt < 8; nt++)
        #pragma unroll
        for (int j = 0; j < 4; j++) O[nt][j] = 0.0f;

    load_chunk(0, 0);
    load_chunk(1, 1);
    for (int c = 0; c < NKV; c++) {
        const int s = c % 3;
        if (c == NKV - 1) CP_WAIT0(); else CP_WAIT1();
        __syncthreads();
        if (c + 2 < NKV) load_chunk(c + 2, (c + 2) % 3);

        const uint32_t st = sb + s * AT_STAGEB;

        // ---- S = Q K^T (3-term), 8 keygroups of 16 keys ----
        float sacc[8][8];
        #pragma unroll
        for (int kg = 0; kg < 8; kg++)
            #pragma unroll
            for (int j = 0; j < 8; j++) sacc[kg][j] = 0.0f;

        #pragma unroll
        for (int kg = 0; kg < 8; kg++) {
            #pragma unroll
            for (int ks = 0; ks < 4; ks++) {
                uint32_t bh[4], bl[4];
                uint32_t ah = st + 0 * AT_MATB + (kg * 16 + b_row) * AT_SB + (ks * 16 + b_kof) * 2;
                uint32_t al = st + 1 * AT_MATB + (kg * 16 + b_row) * AT_SB + (ks * 16 + b_kof) * 2;
                LDSM_X4(bh[0], bh[1], bh[2], bh[3], ah);
                LDSM_X4(bl[0], bl[1], bl[2], bl[3], al);
                MMA16816(&sacc[kg][0], qfh[ks], bh);
                MMA16816(&sacc[kg][4], qfh[ks], bh + 2);
                MMA16816(&sacc[kg][0], qfh[ks], bl);
                MMA16816(&sacc[kg][4], qfh[ks], bl + 2);
                MMA16816(&sacc[kg][0], qfl[ks], bh);
                MMA16816(&sacc[kg][4], qfl[ks], bh + 2);
            }
        }

        // ---- online softmax (rows r and r+8) ----
        float mx0 = -3.0e38f, mx1 = -3.0e38f;
        #pragma unroll
        for (int kg = 0; kg < 8; kg++) {
            mx0 = fmaxf(mx0, fmaxf(fmaxf(sacc[kg][0], sacc[kg][1]),
                                   fmaxf(sacc[kg][4], sacc[kg][5])));
            mx1 = fmaxf(mx1, fmaxf(fmaxf(sacc[kg][2], sacc[kg][3]),
                                   fmaxf(sacc[kg][6], sacc[kg][7])));
        }
        mx0 = fmaxf(mx0, __shfl_xor_sync(0xffffffff, mx0, 1));
        mx0 = fmaxf(mx0, __shfl_xor_sync(0xffffffff, mx0, 2));
        mx1 = fmaxf(mx1, __shfl_xor_sync(0xffffffff, mx1, 1));
        mx1 = fmaxf(mx1, __shfl_xor_sync(0xffffffff, mx1, 2));

        float mn0 = fmaxf(m0, mx0), mn1 = fmaxf(m1, mx1);
        float al0 = __expf(m0 - mn0), al1 = __expf(m1 - mn1);
        m0 = mn0; m1 = mn1;

        float rs0 = 0.0f, rs1 = 0.0f;
        uint32_t pfh[8][4], pfl[8][4];
        #pragma unroll
        for (int kg = 0; kg < 8; kg++) {
            float p0 = __expf(sacc[kg][0] - mn0), p1 = __expf(sacc[kg][1] - mn0);
            float p2 = __expf(sacc[kg][2] - mn1), p3 = __expf(sacc[kg][3] - mn1);
            float p4 = __expf(sacc[kg][4] - mn0), p5 = __expf(sacc[kg][5] - mn0);
            float p6 = __expf(sacc[kg][6] - mn1), p7 = __expf(sacc[kg][7] - mn1);
            rs0 += p0 + p1 + p4 + p5;
            rs1 += p2 + p3 + p6 + p7;
            split2(p0, p1, pfh[kg][0], pfl[kg][0]);
            split2(p2, p3, pfh[kg][1], pfl[kg][1]);
            split2(p4, p5, pfh[kg][2], pfl[kg][2]);
            split2(p6, p7, pfh[kg][3], pfl[kg][3]);
        }
        rs0 += __shfl_xor_sync(0xffffffff, rs0, 1);
        rs0 += __shfl_xor_sync(0xffffffff, rs0, 2);
        rs1 += __shfl_xor_sync(0xffffffff, rs1, 1);
        rs1 += __shfl_xor_sync(0xffffffff, rs1, 2);
        l0 = l0 * al0 + rs0;
        l1 = l1 * al1 + rs1;

        #pragma unroll
        for (int nt = 0; nt < 8; nt++) {
            O[nt][0] *= al0; O[nt][1] *= al0;
            O[nt][2] *= al1; O[nt][3] *= al1;
        }

        // ---- O += P V (3-term) ----
        #pragma unroll
        for (int kg = 0; kg < 8; kg++) {
            #pragma unroll
            for (int dt = 0; dt < 4; dt++) {
                uint32_t vh[4], vl[4];
                uint32_t ahh = st + 2 * AT_MATB + (kg * 16 + v_row) * AT_SB + (dt * 16 + v_cof) * 2;
                uint32_t all = st + 3 * AT_MATB + (kg * 16 + v_row) * AT_SB + (dt * 16 + v_cof) * 2;
                LDSM_X4_T(vh[0], vh[1], vh[2], vh[3], ahh);
                LDSM_X4_T(vl[0], vl[1], vl[2], vl[3], all);
                MMA16816(O[2*dt],     pfh[kg], vh);
                MMA16816(O[2*dt + 1], pfh[kg], vh + 2);
                MMA16816(O[2*dt],     pfh[kg], vl);
                MMA16816(O[2*dt + 1], pfh[kg], vl + 2);
                MMA16816(O[2*dt],     pfl[kg], vh);
                MMA16816(O[2*dt + 1], pfl[kg], vh + 2);
            }
        }
    }

    // ---- epilogue: normalize, write outproj A-pattern (hi,hi,lo) ----
    const float inv0 = 1.0f / l0, inv1 = 1.0f / l1;
    const int bb = head >> 4, hh = head & 15;
    const int mr0 = (qb + wr0 + r) * 2 + bb;
    const int mr8 = (qb + wr0 + r + 8) * 2 + bb;
    #pragma unroll
    for (int nt = 0; nt < 8; nt++) {
        const int e = hh * 64 + nt * 8 + cb;
        uint32_t hp, lp;
        split2(O[nt][0] * inv0, O[nt][1] * inv0, hp, lp);
        __nv_bfloat16* base = g_attna + (size_t)mr0 * KEFF + e;
        *(uint32_t*)(base)           = hp;
        *(uint32_t*)(base + EMB)     = hp;
        *(uint32_t*)(base + 2*EMB)   = lp;
        split2(O[nt][2] * inv1, O[nt][3] * inv1, hp, lp);
        base = g_attna + (size_t)mr8 * KEFF + e;
        *(uint32_t*)(base)           = hp;
        *(uint32_t*)(base + EMB)     = hp;
        *(uint32_t*)(base + 2*EMB)   = lp;
    }
}

// ---------------------------------------------------------------------------
extern "C" void kernel_launch(void* const* d_in, const int* in_sizes, int n_in,
                              void* d_out, int out_size) {
    (void)in_sizes; (void)n_in; (void)out_size;
    const float* x     = (const float*)d_in[0];
    const float* w_in  = (const float*)d_in[1];
    const float* b_in  = (const float*)d_in[2];
    const float* w_out = (const float*)d_in[3];
    const float* b_out = (const float*)d_in[4];
    float* out = (float*)d_out;

    cudaFuncSetAttribute(gemm_kernel<0>, cudaFuncAttributeMaxDynamicSharedMemorySize, G_SMEM);
    cudaFuncSetAttribute(gemm_kernel<1>, cudaFuncAttributeMaxDynamicSharedMemorySize, G_SMEM);
    cudaFuncSetAttribute(attn_tc_kernel, cudaFuncAttributeMaxDynamicSharedMemorySize, AT_SMEM);

    __nv_bfloat16 *gxa, *gwin, *gwout, *gattna;
    cudaGetSymbolAddress((void**)&gxa, g_xa);
    cudaGetSymbolAddress((void**)&gwin, g_win);
    cudaGetSymbolAddress((void**)&gwout, g_wout);
    cudaGetSymbolAddress((void**)&gattna, g_attna);

    // 1) convert operands to bf16x3
    cvt_kernel<<<MROWS, 256>>>(x, gxa, 0);
    cvt_kernel<<<THREE_E, 256>>>(w_in, gwin, 1);
    cvt_kernel<<<EMB, 256>>>(w_out, gwout, 1);
    // 2) QKV projection -> bf16 hi/lo q/k/v
    gemm_kernel<0><<<dim3(THREE_E / TILE_N, MROWS / TILE_M), 256, G_SMEM>>>(gxa, gwin, b_in, nullptr);
    // 3) tensor-core flash attention -> g_attna (A-pattern)
    attn_tc_kernel<<<dim3(TLEN / 128, BH), 256, AT_SMEM>>>();
    // 4) output projection
    gemm_kernel<1><<<dim3(EMB / TILE_N, MROWS / TILE_M), 256, G_SMEM>>>(gattna, gwout, b_out, out);
}